// round 16
// baseline (speedup 1.0000x reference)
#include <cuda_runtime.h>
#include <cuda_fp16.h>
#include <cstdint>

// Problem constants
#define Bsz  2
#define Tn   1024
#define Cn   1024
#define Hn   16
#define HDn  64
#define Vn   50257
#define BTn  2048
#define NBH  32          // B*H
#define NBN  197         // ceil(Vn/256)

// Chunked, pre-swizzled fp16 operands.
// A-chunks: [.. ][kc][row:128][64 halves], B-chunks: [..][kc][row:256][64 halves]
__device__ __align__(128) __half g_xh[BTn * Cn];                 // embed out (A of QKV)
__device__ __align__(128) __half g_wqkvh[3 * 4 * 16 * 256 * 64]; // Wq/Wk/Wv (B of QKV)
__device__ __align__(128) __half g_qh[NBH * 8 * 128 * 64];       // Q [bh][sb][r][d]
__device__ __align__(128) __half g_kh[NBH * 8 * 128 * 64];       // K [bh][sb][r][d]
__device__ __align__(128) __half g_vt[NBH * 16 * 64 * 64];       // V^T [bh][skc][d][s]
__device__ __align__(128) __half g_ah[BTn * Cn];                 // attn out (A of logits)
__device__ __align__(128) __half g_wh[(size_t)NBN * 16 * 256 * 64]; // W_lm (B of logits)

// ===========================================================================
// helpers (sm_80/sm_90 baseline ISA)
// ===========================================================================
__device__ __forceinline__ uint32_t smem_u32(const void* p) {
    return (uint32_t)__cvta_generic_to_shared(p);
}
__device__ __forceinline__ void mma16(float* c, const unsigned* a, const unsigned* b) {
    asm volatile(
        "mma.sync.aligned.m16n8k16.row.col.f32.f16.f16.f32 "
        "{%0,%1,%2,%3},{%4,%5,%6,%7},{%8,%9},{%0,%1,%2,%3};"
        : "+f"(c[0]), "+f"(c[1]), "+f"(c[2]), "+f"(c[3])
        : "r"(a[0]), "r"(a[1]), "r"(a[2]), "r"(a[3]), "r"(b[0]), "r"(b[1]));
}
__device__ __forceinline__ void ldsm4(unsigned& r0, unsigned& r1, unsigned& r2,
                                      unsigned& r3, uint32_t addr) {
    asm volatile("ldmatrix.sync.aligned.m8n8.x4.shared.b16 {%0,%1,%2,%3}, [%4];"
                 : "=r"(r0), "=r"(r1), "=r"(r2), "=r"(r3) : "r"(addr));
}
__device__ __forceinline__ void bulk_g2s(uint32_t dst, const void* src, int bytes,
                                         uint32_t mbar) {
    asm volatile(
        "cp.async.bulk.shared::cluster.global.mbarrier::complete_tx::bytes "
        "[%0], [%1], %2, [%3];"
        :: "r"(dst), "l"(src), "r"(bytes), "r"(mbar) : "memory");
}
#define MBAR_INIT(mbar, cnt) \
    asm volatile("mbarrier.init.shared.b64 [%0], %1;" \
                 :: "r"((uint32_t)(mbar)), "r"((uint32_t)(cnt)) : "memory")
#define MBAR_EXPECT(mbar, tx) \
    asm volatile("mbarrier.arrive.expect_tx.shared.b64 _, [%0], %1;" \
                 :: "r"((uint32_t)(mbar)), "r"((uint32_t)(tx)) : "memory")
#define MBAR_WAIT(mbar, parity) do {                                          \
    uint32_t _m = (uint32_t)(mbar);                                           \
    uint32_t _p = (uint32_t)(parity);                                         \
    asm volatile(                                                             \
        "{\n\t.reg .pred P1;\n\t"                                             \
        "WAIT_LOOP_%=:\n\t"                                                   \
        "mbarrier.try_wait.parity.acquire.cta.shared::cta.b64 P1, [%0], %1, 0x989680;\n\t" \
        "@P1 bra.uni WAIT_DONE_%=;\n\t"                                       \
        "bra.uni WAIT_LOOP_%=;\n\t"                                           \
        "WAIT_DONE_%=:\n\t}"                                                  \
        :: "r"(_m), "r"(_p) : "memory");                                      \
} while (0)

__device__ __forceinline__ unsigned packh2(float x, float y) {
    __half2 h = __floats2half2_rn(x, y);
    return *(unsigned*)&h;
}

// ---------------------------------------------------------------------------
// 1) Embedding -> fp16 chunked+swizzled A layout (g_xh)
__global__ __launch_bounds__(256) void k_embed(const int* __restrict__ idx,
                                               const float* __restrict__ tok,
                                               const float* __restrict__ pos) {
    int i = blockIdx.x;                   // bt row
    int t = i & (Tn - 1);
    int token = idx[i];
    const float4* te = (const float4*)(tok + (size_t)token * Cn);
    const float4* pe = (const float4*)(pos + (size_t)t * Cn);
    int tid = threadIdx.x;
    float4 a = te[tid], b = pe[tid];
    uint2 o;
    o.x = packh2(a.x + b.x, a.y + b.y);
    o.y = packh2(a.z + b.z, a.w + b.w);
    int r = i & 127, bm = i >> 7;
    int kc = tid >> 4;                    // k = tid*4; kc = k>>6
    int c16 = (tid >> 1) & 7;
    int hsel = tid & 1;
    size_t base = ((size_t)(bm * 16 + kc)) * 16384;
    uint32_t off = (uint32_t)r * 128 + ((unsigned)(c16 ^ (r & 7)) << 4) + hsel * 8;
    *(uint2*)((char*)g_xh + base + off) = o;
}

// ---------------------------------------------------------------------------
// 1b) W_lm -> fp16, tile-chunked + SW128-swizzled B layout. Grid-stride so it
//     trickles alongside the attention chain on the side stream.
__global__ __launch_bounds__(256) void k_w2h(const float* __restrict__ W) {
    for (int gid = blockIdx.x * 256 + threadIdx.x; gid < Vn * 128;
         gid += gridDim.x * 256) {
        int v = gid >> 7, g8 = gid & 127;             // kk = g8*8
        const float4* s = (const float4*)(W + (size_t)v * Cn + g8 * 8);
        float4 x = s[0], y = s[1];
        uint4 o;
        o.x = packh2(x.x, x.y); o.y = packh2(x.z, x.w);
        o.z = packh2(y.x, y.y); o.w = packh2(y.z, y.w);
        int bn = v >> 8, r = v & 255;
        int kc = g8 >> 3, c16 = g8 & 7;
        size_t chunkB = (((size_t)bn * 16 + kc) * (256 * 64)) * 2;
        uint32_t off = (uint32_t)r * 128 + ((unsigned)(c16 ^ (r & 7)) << 4);
        *(uint4*)((char*)g_wh + chunkB + off) = o;
    }
}

// ---------------------------------------------------------------------------
// 1c) Wq/Wk/Wv -> transposed fp16 chunked B layout (n=(h,d) rows, k=c).
__global__ __launch_bounds__(256) void k_wqkv(const float* __restrict__ Wq,
                                              const float* __restrict__ Wk,
                                              const float* __restrict__ Wv) {
    int u = blockIdx.x * 4 + (threadIdx.x >> 6);   // 0..6143
    int d = threadIdx.x & 63;
    int mat = u >> 11;
    int rem = u & 2047;
    int h = rem >> 7;
    int kc = (rem >> 3) & 15;
    int c16 = rem & 7;
    const float* W = (mat == 0) ? Wq : (mat == 1) ? Wk : Wv;
    const float* Wb = W + (size_t)h * (Cn * HDn) + d;
    float vals[8];
#pragma unroll
    for (int j = 0; j < 8; j++) {
        int c = kc * 64 + c16 * 8 + j;
        vals[j] = Wb[(size_t)c * HDn];
    }
    uint4 o;
    o.x = packh2(vals[0], vals[1]); o.y = packh2(vals[2], vals[3]);
    o.z = packh2(vals[4], vals[5]); o.w = packh2(vals[6], vals[7]);
    int bnAll = mat * 4 + (h >> 2);
    int r = (h & 3) * 64 + d;
    size_t chunkB = (((size_t)bnAll * 16 + kc) * (256 * 64)) * 2;
    uint32_t off = (uint32_t)r * 128 + ((unsigned)(c16 ^ (r & 7)) << 4);
    *(uint4*)((char*)g_wqkvh + chunkB + off) = o;
}

// ===========================================================================
// Shared fp16 bulk-pipeline GEMM pieces
// ===========================================================================
#define LKCH 16                          // K chunks of 64
#define A_CH_BYTES (128 * 128)           // 16KB
#define B_CH_BYTES (256 * 128)           // 32KB
#define LSTG_BYTES (A_CH_BYTES + B_CH_BYTES)   // 49152
#define LOG_SMEM (3 * LSTG_BYTES)        // 147456
#define OPITCH 264                       // f32 pitch for epilogue staging

struct Frags { unsigned a[4][4]; unsigned b[8][2]; };

__device__ __forceinline__ void load_frags(Frags& f, uint32_t sb, int kt,
                                           uint32_t aAddr0, uint32_t bAddr0,
                                           int gA16, int gB16, int l7) {
    const uint32_t xA = ((uint32_t)((kt * 2 + gA16) ^ l7)) << 4;
    const uint32_t xB = ((uint32_t)((kt * 2 + gB16) ^ l7)) << 4;
#pragma unroll
    for (int mt = 0; mt < 4; mt++)
        ldsm4(f.a[mt][0], f.a[mt][1], f.a[mt][2], f.a[mt][3],
              sb + aAddr0 + mt * (16 * 128) + xA);
#pragma unroll
    for (int np = 0; np < 4; np++)
        ldsm4(f.b[2 * np][0], f.b[2 * np][1], f.b[2 * np + 1][0], f.b[2 * np + 1][1],
              sb + bAddr0 + np * (16 * 128) + xB);
}

__device__ __forceinline__ void gemm_mainloop(float (&c)[4][8][4], uint32_t sbase,
                                              uint32_t mb0, const char* gA,
                                              const char* gB, int tid,
                                              uint32_t aAddr0, uint32_t bAddr0,
                                              int gA16, int gB16, int l7) {
    Frags fr[2];
    MBAR_WAIT(mb0, 0);
    load_frags(fr[0], sbase, 0, aAddr0, bAddr0, gA16, gB16, l7);

    for (int kc = 0; kc < LKCH; kc++) {
        const uint32_t sb = sbase + (kc % 3) * LSTG_BYTES;
#pragma unroll
        for (int kt = 0; kt < 4; kt++) {
            const int cur = kt & 1;
            if (kt < 3)
                load_frags(fr[cur ^ 1], sb, kt + 1, aAddr0, bAddr0, gA16, gB16, l7);
#pragma unroll
            for (int mt = 0; mt < 4; mt++)
#pragma unroll
                for (int nt = 0; nt < 8; nt++) mma16(c[mt][nt], fr[cur].a[mt], fr[cur].b[nt]);
        }
        __syncthreads();
        if (tid == 0 && kc + 3 < LKCH) {
            int s = kc % 3;
            uint32_t m = mb0 + s * 8;
            uint32_t dst = sbase + s * LSTG_BYTES;
            MBAR_EXPECT(m, LSTG_BYTES);
            bulk_g2s(dst, gA + (size_t)(kc + 3) * A_CH_BYTES, A_CH_BYTES, m);
            bulk_g2s(dst + A_CH_BYTES, gB + (size_t)(kc + 3) * B_CH_BYTES, B_CH_BYTES, m);
        }
        if (kc + 1 < LKCH) {
            MBAR_WAIT(mb0 + ((kc + 1) % 3) * 8, ((kc + 1) / 3) & 1);
            load_frags(fr[0], sbase + ((kc + 1) % 3) * LSTG_BYTES, 0,
                       aAddr0, bAddr0, gA16, gB16, l7);
        }
    }
}

// ---------------------------------------------------------------------------
// 2) QKV via fp16 bulk pipeline. grid (16, 12): bn 0-3 -> q, 4-7 -> k, 8-11 -> v.
__global__ __launch_bounds__(256, 1) void k_qkv_h() {
    extern __shared__ __align__(128) char sm[];
    __shared__ __align__(8) unsigned long long s_mb[3];
    const int tid = threadIdx.x, lane = tid & 31, wid = tid >> 5;
    const int bm = blockIdx.x, bnAll = blockIdx.y;
    const uint32_t sbase = smem_u32(sm);
    const uint32_t mb0 = smem_u32(&s_mb[0]);

    if (tid == 0) {
        MBAR_INIT(mb0, 1);
        MBAR_INIT(mb0 + 8, 1);
        MBAR_INIT(mb0 + 16, 1);
    }
    __syncthreads();

    const char* gA = (const char*)g_xh + ((size_t)bm * LKCH) * A_CH_BYTES;
    const char* gB = (const char*)g_wqkvh + ((size_t)bnAll * LKCH) * B_CH_BYTES;

    if (tid == 0) {
#pragma unroll
        for (int s = 0; s < 3; s++) {
            uint32_t m = mb0 + s * 8;
            uint32_t dst = sbase + s * LSTG_BYTES;
            MBAR_EXPECT(m, LSTG_BYTES);
            bulk_g2s(dst, gA + (size_t)s * A_CH_BYTES, A_CH_BYTES, m);
            bulk_g2s(dst + A_CH_BYTES, gB + (size_t)s * B_CH_BYTES, B_CH_BYTES, m);
        }
    }

    float c[4][8][4];
#pragma unroll
    for (int mt = 0; mt < 4; mt++)
#pragma unroll
        for (int nt = 0; nt < 8; nt++)
#pragma unroll
            for (int e = 0; e < 4; e++) c[mt][nt][e] = 0.f;

    const int wm0 = (wid >> 2) * 64, wn0 = (wid & 3) * 64;
    const int l7 = lane & 7;
    const uint32_t aAddr0 = (uint32_t)(wm0 + (lane & 15)) * 128;
    const uint32_t bAddr0 = A_CH_BYTES +
                            (uint32_t)(wn0 + ((lane >> 4) << 3) + l7) * 128;
    const int gA16 = lane >> 4, gB16 = (lane >> 3) & 1;

    gemm_mainloop(c, sbase, mb0, gA, gB, tid, aAddr0, bAddr0, gA16, gB16, l7);

    // stage (scaled) accum to SMEM f32
    const int mat = bnAll >> 2;
    const float sc = (mat == 0) ? 0.03125f : 1.0f;
    __syncthreads();
    float* so = (float*)sm;
    const int g = lane >> 2, tig = lane & 3;
#pragma unroll
    for (int mt = 0; mt < 4; mt++)
#pragma unroll
        for (int e2 = 0; e2 < 2; e2++) {
            int rl = wm0 + mt * 16 + g + e2 * 8;
#pragma unroll
            for (int nt = 0; nt < 8; nt++) {
                int cl = wn0 + nt * 8 + 2 * tig;
                float2 w;
                w.x = c[mt][nt][e2 * 2 + 0] * sc;
                w.y = c[mt][nt][e2 * 2 + 1] * sc;
                *(float2*)(so + rl * OPITCH + cl) = w;
            }
        }
    __syncthreads();

    const int b = bm >> 3;            // batch of this 128-row tile
    if (mat < 2) {
        // Q/K: [bh][sb][r:128][64] chunks; warp handles rows wid*16..+15
        __half* dst = (mat == 0) ? g_qh : g_kh;
        const int seg = lane >> 3, g8 = lane & 7;
        const int h = (bnAll & 3) * 4 + seg;
        const int sb = bm & 7;
#pragma unroll 1
        for (int rr = 0; rr < 16; rr++) {
            int rl = wid * 16 + rr;
            const float* srow = so + rl * OPITCH + seg * 64 + g8 * 8;
            uint4 o;
            o.x = packh2(srow[0], srow[1]); o.y = packh2(srow[2], srow[3]);
            o.z = packh2(srow[4], srow[5]); o.w = packh2(srow[6], srow[7]);
            size_t chunk = ((size_t)((b * 16 + h) * 8 + sb)) * 16384;
            uint32_t off = (uint32_t)rl * 128 + ((unsigned)(g8 ^ (rl & 7)) << 4);
            *(uint4*)((char*)dst + chunk + off) = o;
        }
    } else {
        // V^T: [bh][skc:16][d:64][64 s] chunks of 8KB
#pragma unroll 1
        for (int it = 0; it < 16; it++) {
            int u = tid * 16 + it;
            int seg = u >> 10;
            int d = (u >> 4) & 63;
            int sg = u & 15;              // s granule of 8 within 128 rows
            const float* scol = so + (sg * 8) * OPITCH + seg * 64 + d;
            uint4 o;
            o.x = packh2(scol[0], scol[OPITCH]);
            o.y = packh2(scol[2 * OPITCH], scol[3 * OPITCH]);
            o.z = packh2(scol[4 * OPITCH], scol[5 * OPITCH]);
            o.w = packh2(scol[6 * OPITCH], scol[7 * OPITCH]);
            int h = (bnAll & 3) * 4 + seg;
            int skc = (bm & 7) * 2 + (sg >> 3);
            size_t chunk = ((size_t)((b * 16 + h) * 16 + skc)) * 8192;
            uint32_t off = (uint32_t)d * 128 + ((unsigned)((sg & 7) ^ (d & 7)) << 4);
            *(uint4*)((char*)g_vt + chunk + off) = o;
        }
    }
}

// ---------------------------------------------------------------------------
// 3) Fused flash attention with PAIRED tiles: CTA (pair, bh) handles
//    bm_hi = 7-pair then bm_lo = pair -> exactly 9 kv-blocks per CTA.
#define FQ_BYTES 16384
#define FKV_BYTES 32768                  // K 16KB + V^T 16KB
#define FLASH_SMEM (FQ_BYTES + 2 * FKV_BYTES)   // 81920

__global__ __launch_bounds__(256, 1) void k_flash() {
    extern __shared__ __align__(128) char sm[];
    __shared__ __align__(8) unsigned long long s_mb[3];   // Q, stage0, stage1
    const int tid = threadIdx.x, lane = tid & 31, wid = tid >> 5;
    const int pair = blockIdx.x >> 5;         // 0..3
    const int bh = blockIdx.x & 31;
    const int bm_hi = 7 - pair, bm_lo = pair; // (bm_hi+1)+(bm_lo+1) = 9
    const uint32_t sbase = smem_u32(sm);
    const uint32_t mbQ = smem_u32(&s_mb[0]);

    const char* gQb = (const char*)g_qh + ((size_t)bh * 8) * 16384;
    const char* gK = (const char*)g_kh + ((size_t)bh * 8) * 16384;
    const char* gV = (const char*)g_vt + ((size_t)bh * 16) * 8192;

    if (tid == 0) {
        MBAR_INIT(mbQ, 1);
        MBAR_INIT(mbQ + 8, 1);
        MBAR_INIT(mbQ + 16, 1);
    }
    __syncthreads();
    if (tid == 0) {
        MBAR_EXPECT(mbQ, FQ_BYTES);
        bulk_g2s(sbase, gQb + (size_t)bm_hi * 16384, FQ_BYTES, mbQ);
        MBAR_EXPECT(mbQ + 8, FKV_BYTES);
        bulk_g2s(sbase + FQ_BYTES, gK, 16384, mbQ + 8);
        bulk_g2s(sbase + FQ_BYTES + 16384, gV, 16384, mbQ + 8);
        MBAR_EXPECT(mbQ + 16, FKV_BYTES);
        bulk_g2s(sbase + FQ_BYTES + FKV_BYTES, gK + 16384, 16384, mbQ + 16);
        bulk_g2s(sbase + FQ_BYTES + FKV_BYTES + 16384, gV + 16384, 16384, mbQ + 16);
    }

    const int wm = wid * 16;
    const int l7 = lane & 7;
    const int g = lane >> 2, tig = lane & 3;
    const uint32_t aAddr0 = (uint32_t)(wm + (lane & 15)) * 128;
    const uint32_t rowBB = (uint32_t)(((lane >> 4) << 3) + l7) * 128;
    const int gA16 = lane >> 4, gB16 = (lane >> 3) & 1;

    float m0 = -1e30f, m1 = -1e30f, l0 = 0.f, l1 = 0.f;
    float o[8][4];
#pragma unroll
    for (int nt = 0; nt < 8; nt++)
#pragma unroll
        for (int e = 0; e < 4; e++) o[nt][e] = 0.f;

    unsigned aq[4][4];
    MBAR_WAIT(mbQ, 0);
#pragma unroll
    for (int kt = 0; kt < 4; kt++) {
        uint32_t xA = ((uint32_t)((kt * 2 + gA16) ^ l7)) << 4;
        ldsm4(aq[kt][0], aq[kt][1], aq[kt][2], aq[kt][3], sbase + aAddr0 + xA);
    }
    __syncthreads();                 // all warps have read Q_hi from smem
    if (tid == 0) {                  // prefetch Q_lo into the (now free) Q buffer
        MBAR_EXPECT(mbQ, FQ_BYTES);
        bulk_g2s(sbase, gQb + (size_t)bm_lo * 16384, FQ_BYTES, mbQ);
    }

    const int b = bh >> 4, h = bh & 15;

    auto write_out = [&](int bm_out) {
        const float inv0 = 1.0f / l0, inv1 = 1.0f / l1;
        const size_t chunkB = ((size_t)((b * 8 + bm_out) * 16 + h)) * 16384;
#pragma unroll
        for (int nt = 0; nt < 8; nt++)
#pragma unroll
            for (int e = 0; e < 4; e++) {
                int rl = wm + g + ((e >= 2) ? 8 : 0);
                int d = nt * 8 + 2 * tig + (e & 1);
                float val = o[nt][e] * ((e >= 2) ? inv1 : inv0);
                uint32_t off = (uint32_t)rl * 128 +
                               ((unsigned)(((d >> 3) ^ (rl & 7))) << 4) + (d & 7) * 2;
                *(__half*)((char*)g_ah + chunkB + off) = __float2half_rn(val);
            }
    };

    for (int i = 0; i < 9; i++) {
        const int in_hi = (i <= bm_hi);
        const int cur_bm = in_hi ? bm_hi : bm_lo;
        const int j = in_hi ? i : (i - bm_hi - 1);
        const uint32_t stg = sbase + FQ_BYTES + (i & 1) * FKV_BYTES;
        MBAR_WAIT(mbQ + 8 + (i & 1) * 8, (i >> 1) & 1);

        float s[16][4];
#pragma unroll
        for (int nt = 0; nt < 16; nt++)
#pragma unroll
            for (int e = 0; e < 4; e++) s[nt][e] = 0.f;

#pragma unroll
        for (int kt = 0; kt < 4; kt++) {
            uint32_t xB = ((uint32_t)((kt * 2 + gB16) ^ l7)) << 4;
            unsigned bk[16][2];
#pragma unroll
            for (int np = 0; np < 8; np++)
                ldsm4(bk[2 * np][0], bk[2 * np][1], bk[2 * np + 1][0], bk[2 * np + 1][1],
                      stg + rowBB + np * (16 * 128) + xB);
#pragma unroll
            for (int nt = 0; nt < 16; nt++) mma16(s[nt], aq[kt], bk[nt]);
        }

        if (j == cur_bm) {   // causal mask on diagonal block
#pragma unroll
            for (int nt = 0; nt < 16; nt++) {
                int col = nt * 8 + 2 * tig;
                int r0 = wm + g, r1 = wm + g + 8;
                if (col > r0)     s[nt][0] = -1e30f;
                if (col + 1 > r0) s[nt][1] = -1e30f;
                if (col > r1)     s[nt][2] = -1e30f;
                if (col + 1 > r1) s[nt][3] = -1e30f;
            }
        }

        // online softmax
        float v0 = -1e30f, v1 = -1e30f;
#pragma unroll
        for (int nt = 0; nt < 16; nt++) {
            v0 = fmaxf(v0, fmaxf(s[nt][0], s[nt][1]));
            v1 = fmaxf(v1, fmaxf(s[nt][2], s[nt][3]));
        }
#pragma unroll
        for (int off = 1; off <= 2; off <<= 1) {
            v0 = fmaxf(v0, __shfl_xor_sync(0xffffffffu, v0, off));
            v1 = fmaxf(v1, __shfl_xor_sync(0xffffffffu, v1, off));
        }
        float mn0 = fmaxf(m0, v0), mn1 = fmaxf(m1, v1);
        float sc0 = __expf(m0 - mn0), sc1 = __expf(m1 - mn1);
        float sum0 = 0.f, sum1 = 0.f;
#pragma unroll
        for (int nt = 0; nt < 16; nt++) {
            s[nt][0] = __expf(s[nt][0] - mn0);
            s[nt][1] = __expf(s[nt][1] - mn0);
            s[nt][2] = __expf(s[nt][2] - mn1);
            s[nt][3] = __expf(s[nt][3] - mn1);
            sum0 += s[nt][0] + s[nt][1];
            sum1 += s[nt][2] + s[nt][3];
        }
#pragma unroll
        for (int off = 1; off <= 2; off <<= 1) {
            sum0 += __shfl_xor_sync(0xffffffffu, sum0, off);
            sum1 += __shfl_xor_sync(0xffffffffu, sum1, off);
        }
        l0 = l0 * sc0 + sum0; l1 = l1 * sc1 + sum1;
        m0 = mn0; m1 = mn1;
#pragma unroll
        for (int nt = 0; nt < 8; nt++) {
            o[nt][0] *= sc0; o[nt][1] *= sc0;
            o[nt][2] *= sc1; o[nt][3] *= sc1;
        }

        // pack P as A-fragments
        unsigned pa[8][4];
#pragma unroll
        for (int kt = 0; kt < 8; kt++) {
            pa[kt][0] = packh2(s[2 * kt][0], s[2 * kt][1]);
            pa[kt][1] = packh2(s[2 * kt][2], s[2 * kt][3]);
            pa[kt][2] = packh2(s[2 * kt + 1][0], s[2 * kt + 1][1]);
            pa[kt][3] = packh2(s[2 * kt + 1][2], s[2 * kt + 1][3]);
        }

        // PV: V^T tiles (n=d 64, k=s 128 in two 64-k chunks)
#pragma unroll
        for (int kt = 0; kt < 8; kt++) {
            const uint32_t vb = stg + 16384 + (kt >> 2) * 8192;
            const int kt2 = kt & 3;
            uint32_t xV = ((uint32_t)((kt2 * 2 + gB16) ^ l7)) << 4;
            unsigned bv[8][2];
#pragma unroll
            for (int np = 0; np < 4; np++)
                ldsm4(bv[2 * np][0], bv[2 * np][1], bv[2 * np + 1][0], bv[2 * np + 1][1],
                      vb + rowBB + np * (16 * 128) + xV);
#pragma unroll
            for (int nt = 0; nt < 8; nt++) mma16(o[nt], pa[kt], bv[nt]);
        }

        __syncthreads();
        if (tid == 0 && i + 2 < 9) {
            int jn = (i + 2 <= bm_hi) ? (i + 2) : (i + 2 - bm_hi - 1);
            int st = i & 1;
            uint32_t m = mbQ + 8 + st * 8;
            uint32_t dst = sbase + FQ_BYTES + st * FKV_BYTES;
            MBAR_EXPECT(m, FKV_BYTES);
            bulk_g2s(dst, gK + (size_t)jn * 16384, 16384, m);
            bulk_g2s(dst + 16384, gV + (size_t)jn * 16384, 16384, m);
        }

        if (i == bm_hi) {
            write_out(bm_hi);
            m0 = -1e30f; m1 = -1e30f; l0 = 0.f; l1 = 0.f;
#pragma unroll
            for (int nt = 0; nt < 8; nt++)
#pragma unroll
                for (int e = 0; e < 4; e++) o[nt][e] = 0.f;
            MBAR_WAIT(mbQ, 1);
#pragma unroll
            for (int kt = 0; kt < 4; kt++) {
                uint32_t xA = ((uint32_t)((kt * 2 + gA16) ^ l7)) << 4;
                ldsm4(aq[kt][0], aq[kt][1], aq[kt][2], aq[kt][3], sbase + aAddr0 + xA);
            }
        }
    }

    write_out(bm_lo);
}

// ---------------------------------------------------------------------------
// 4) LM head: PERSISTENT fp16 bulk pipeline v2. 148 CTAs; CTA c handles tiles
//    t = c + w*148 (bm = t&15, bn = t>>4). Flat chunk counter rolls the
//    3-stage ring across tile boundaries. FIX vs R15: cross-chunk fragment
//    preload restored (next chunk's kt=0 frags loaded right after its mbar
//    wait, BEFORE any epilogue work), bias via s_bias.
#define EPI_OFF   (3 * LSTG_BYTES)              // 147456
#define EPI_PITCH 264
#define PLOG_SMEM (EPI_OFF + 64 * EPI_PITCH * 4) // 215040

__global__ __launch_bounds__(256, 1) void k_logits_p(const float* __restrict__ blm,
                                                     float* __restrict__ out) {
    extern __shared__ __align__(128) char sm[];
    __shared__ float s_bias[256];
    __shared__ __align__(8) unsigned long long s_mb[3];
    const int tid = threadIdx.x, lane = tid & 31, wid = tid >> 5;
    const uint32_t sbase = smem_u32(sm);
    const uint32_t mb0 = smem_u32(&s_mb[0]);
    const int cta = blockIdx.x;

    if (tid == 0) {
        MBAR_INIT(mb0, 1);
        MBAR_INIT(mb0 + 8, 1);
        MBAR_INIT(mb0 + 16, 1);
    }
    __syncthreads();

    const int ntiles = (16 * NBN - cta + 147) / 148;   // 21 or 22
    const int nchunks = ntiles * LKCH;

    const int wm0 = (wid >> 2) * 64, wn0 = (wid & 3) * 64;
    const int l7 = lane & 7;
    const uint32_t aAddr0 = (uint32_t)(wm0 + (lane & 15)) * 128;
    const uint32_t bAddr0 = A_CH_BYTES +
                            (uint32_t)(wn0 + ((lane >> 4) << 3) + l7) * 128;
    const int gA16 = lane >> 4, gB16 = (lane >> 3) & 1;
    const int g = lane >> 2, tig = lane & 3;

    auto issue = [&](int p) {
        int t = cta + (p >> 4) * 148;
        int kc = p & 15;
        const char* gA = (const char*)g_ah + ((size_t)(t & 15) * LKCH + kc) * A_CH_BYTES;
        const char* gB = (const char*)g_wh + ((size_t)(t >> 4) * LKCH + kc) * B_CH_BYTES;
        uint32_t m = mb0 + (p % 3) * 8;
        uint32_t dst = sbase + (p % 3) * LSTG_BYTES;
        MBAR_EXPECT(m, LSTG_BYTES);
        bulk_g2s(dst, gA, A_CH_BYTES, m);
        bulk_g2s(dst + A_CH_BYTES, gB, B_CH_BYTES, m);
    };

    if (tid == 0)
        for (int p = 0; p < 3 && p < nchunks; p++) issue(p);

    float c[4][8][4];
#pragma unroll
    for (int mt = 0; mt < 4; mt++)
#pragma unroll
        for (int nt = 0; nt < 8; nt++)
#pragma unroll
            for (int e = 0; e < 4; e++) c[mt][nt][e] = 0.f;

    Frags fr[2];
    MBAR_WAIT(mb0, 0);
    load_frags(fr[0], sbase, 0, aAddr0, bAddr0, gA16, gB16, l7);

    for (int p = 0; p < nchunks; p++) {
        const uint32_t sb = sbase + (p % 3) * LSTG_BYTES;
#pragma unroll
        for (int kt = 0; kt < 4; kt++) {
            const int cur = kt & 1;
            if (kt < 3)
                load_frags(fr[cur ^ 1], sb, kt + 1, aAddr0, bAddr0, gA16, gB16, l7);
#pragma unroll
            for (int mt = 0; mt < 4; mt++)
#pragma unroll
                for (int nt = 0; nt < 8; nt++) mma16(c[mt][nt], fr[cur].a[mt], fr[cur].b[nt]);
        }
        __syncthreads();
        if (tid == 0 && p + 3 < nchunks) issue(p + 3);
        // cross-chunk fragment preload (the R15 regression fix): grab the next
        // chunk's kt=0 frags NOW so mma never waits on LDSM, and the epilogue
        // below overlaps already-satisfied loads.
        if (p + 1 < nchunks) {
            MBAR_WAIT(mb0 + ((p + 1) % 3) * 8, ((p + 1) / 3) & 1);
            load_frags(fr[0], sbase + ((p + 1) % 3) * LSTG_BYTES, 0,
                       aAddr0, bAddr0, gA16, gB16, l7);
        }

        if ((p & 15) == 15) {
            // tile complete: epilogue (ring loads for the next tile in flight)
            int t = cta + (p >> 4) * 148;
            int bm = t & 15, bn = t >> 4;
            {
                int gc = bn * 256 + tid;
                s_bias[tid] = (gc < Vn) ? blm[gc] : 0.f;
            }
            float* so = (float*)(sm + EPI_OFF);
            const int myhalf = wid >> 2;
#pragma unroll 1
            for (int half = 0; half < 2; half++) {
                if (myhalf == half) {
#pragma unroll
                    for (int mt = 0; mt < 4; mt++)
#pragma unroll
                        for (int e2 = 0; e2 < 2; e2++) {
                            int rl = mt * 16 + g + e2 * 8;   // 0..63
#pragma unroll
                            for (int nt = 0; nt < 8; nt++) {
                                int cl = wn0 + nt * 8 + 2 * tig;
                                float2 w;
                                w.x = c[mt][nt][e2 * 2 + 0];
                                w.y = c[mt][nt][e2 * 2 + 1];
                                *(float2*)(so + rl * EPI_PITCH + cl) = w;
                            }
                        }
                }
                __syncthreads();
#pragma unroll 1
                for (int rr = 0; rr < 8; rr++) {
                    int rl = wid * 8 + rr;
                    int row = bm * 128 + half * 64 + rl;
                    float* orow = out + (size_t)row * Vn;
                    const float* srow = so + rl * EPI_PITCH;
#pragma unroll
                    for (int jj = 0; jj < 8; jj++) {
                        int cl = lane + jj * 32;
                        int col = bn * 256 + cl;
                        if (col < Vn) orow[col] = srow[cl] + s_bias[cl];
                    }
                }
                __syncthreads();
            }
#pragma unroll
            for (int mt = 0; mt < 4; mt++)
#pragma unroll
                for (int nt = 0; nt < 8; nt++)
#pragma unroll
                    for (int e = 0; e < 4; e++) c[mt][nt][e] = 0.f;
        }
    }
}

// ---------------------------------------------------------------------------
extern "C" void kernel_launch(void* const* d_in, const int* in_sizes, int n_in,
                              void* d_out, int out_size) {
    (void)in_sizes; (void)n_in; (void)out_size;
    const int*   idx = (const int*)d_in[0];
    const float* tok = (const float*)d_in[1];
    const float* pos = (const float*)d_in[2];
    const float* Wq  = (const float*)d_in[3];
    const float* Wk  = (const float*)d_in[4];
    const float* Wv  = (const float*)d_in[5];
    const float* Wlm = (const float*)d_in[6];
    const float* blm = (const float*)d_in[7];
    float* out = (float*)d_out;

    cudaFuncSetAttribute(k_logits_p, cudaFuncAttributeMaxDynamicSharedMemorySize,
                         PLOG_SMEM);
    cudaFuncSetAttribute(k_qkv_h, cudaFuncAttributeMaxDynamicSharedMemorySize,
                         LOG_SMEM);
    cudaFuncSetAttribute(k_flash, cudaFuncAttributeMaxDynamicSharedMemorySize,
                         FLASH_SMEM);

    // One-time stream/event setup (runs on the first, non-captured call).
    static cudaStream_t s_side = nullptr;
    static cudaEvent_t ev_fork = nullptr, ev_join = nullptr;
    if (!s_side) {
        cudaStreamCreateWithFlags(&s_side, cudaStreamNonBlocking);
        cudaEventCreateWithFlags(&ev_fork, cudaEventDisableTiming);
        cudaEventCreateWithFlags(&ev_join, cudaEventDisableTiming);
    }

    // Fork: W_lm fp16 conversion trickles alongside the attention chain;
    // only the logits kernel consumes g_wh, so join right before it.
    cudaEventRecord(ev_fork, 0);
    cudaStreamWaitEvent(s_side, ev_fork, 0);
    k_w2h<<<592, 256, 0, s_side>>>(Wlm);
    cudaEventRecord(ev_join, s_side);

    k_wqkv<<<1536, 256>>>(Wq, Wk, Wv);
    k_embed<<<BTn, 256>>>(idx, tok, pos);
    k_qkv_h<<<dim3(16, 12), 256, LOG_SMEM>>>();
    k_flash<<<128, 256, FLASH_SMEM>>>();

    cudaStreamWaitEvent(0, ev_join, 0);
    k_logits_p<<<148, 256, PLOG_SMEM>>>(blm, out);
}

// round 17
// speedup vs baseline: 1.6239x; 1.6239x over previous
#include <cuda_runtime.h>
#include <cuda_fp16.h>
#include <cstdint>

// Problem constants
#define Bsz  2
#define Tn   1024
#define Cn   1024
#define Hn   16
#define HDn  64
#define Vn   50257
#define BTn  2048
#define NBH  32          // B*H
#define NBN  197         // ceil(Vn/256)

// Chunked, pre-swizzled fp16 operands.
// A-chunks: [.. ][kc][row:128][64 halves], B-chunks: [..][kc][row:256][64 halves]
__device__ __align__(128) __half g_xh[BTn * Cn];                 // embed out (A of QKV)
__device__ __align__(128) __half g_wqkvh[3 * 4 * 16 * 256 * 64]; // Wq/Wk/Wv (B of QKV)
__device__ __align__(128) __half g_qh[NBH * 8 * 128 * 64];       // Q [bh][sb][r][d]
__device__ __align__(128) __half g_kh[NBH * 8 * 128 * 64];       // K [bh][sb][r][d]
__device__ __align__(128) __half g_vt[NBH * 16 * 64 * 64];       // V^T [bh][skc][d][s]
__device__ __align__(128) __half g_ah[BTn * Cn];                 // attn out (A of logits)
__device__ __align__(128) __half g_wh[(size_t)NBN * 16 * 256 * 64]; // W_lm (B of logits)

// ===========================================================================
// helpers (sm_80/sm_90 baseline ISA)
// ===========================================================================
__device__ __forceinline__ uint32_t smem_u32(const void* p) {
    return (uint32_t)__cvta_generic_to_shared(p);
}
__device__ __forceinline__ void mma16(float* c, const unsigned* a, const unsigned* b) {
    asm volatile(
        "mma.sync.aligned.m16n8k16.row.col.f32.f16.f16.f32 "
        "{%0,%1,%2,%3},{%4,%5,%6,%7},{%8,%9},{%0,%1,%2,%3};"
        : "+f"(c[0]), "+f"(c[1]), "+f"(c[2]), "+f"(c[3])
        : "r"(a[0]), "r"(a[1]), "r"(a[2]), "r"(a[3]), "r"(b[0]), "r"(b[1]));
}
__device__ __forceinline__ void ldsm4(unsigned& r0, unsigned& r1, unsigned& r2,
                                      unsigned& r3, uint32_t addr) {
    asm volatile("ldmatrix.sync.aligned.m8n8.x4.shared.b16 {%0,%1,%2,%3}, [%4];"
                 : "=r"(r0), "=r"(r1), "=r"(r2), "=r"(r3) : "r"(addr));
}
__device__ __forceinline__ void bulk_g2s(uint32_t dst, const void* src, int bytes,
                                         uint32_t mbar) {
    asm volatile(
        "cp.async.bulk.shared::cluster.global.mbarrier::complete_tx::bytes "
        "[%0], [%1], %2, [%3];"
        :: "r"(dst), "l"(src), "r"(bytes), "r"(mbar) : "memory");
}
#define MBAR_INIT(mbar, cnt) \
    asm volatile("mbarrier.init.shared.b64 [%0], %1;" \
                 :: "r"((uint32_t)(mbar)), "r"((uint32_t)(cnt)) : "memory")
#define MBAR_EXPECT(mbar, tx) \
    asm volatile("mbarrier.arrive.expect_tx.shared.b64 _, [%0], %1;" \
                 :: "r"((uint32_t)(mbar)), "r"((uint32_t)(tx)) : "memory")
#define MBAR_WAIT(mbar, parity) do {                                          \
    uint32_t _m = (uint32_t)(mbar);                                           \
    uint32_t _p = (uint32_t)(parity);                                         \
    asm volatile(                                                             \
        "{\n\t.reg .pred P1;\n\t"                                             \
        "WAIT_LOOP_%=:\n\t"                                                   \
        "mbarrier.try_wait.parity.acquire.cta.shared::cta.b64 P1, [%0], %1, 0x989680;\n\t" \
        "@P1 bra.uni WAIT_DONE_%=;\n\t"                                       \
        "bra.uni WAIT_LOOP_%=;\n\t"                                           \
        "WAIT_DONE_%=:\n\t}"                                                  \
        :: "r"(_m), "r"(_p) : "memory");                                      \
} while (0)

__device__ __forceinline__ unsigned packh2(float x, float y) {
    __half2 h = __floats2half2_rn(x, y);
    return *(unsigned*)&h;
}

// ---------------------------------------------------------------------------
// 1) Embedding -> fp16 chunked+swizzled A layout (g_xh)
__global__ __launch_bounds__(256) void k_embed(const int* __restrict__ idx,
                                               const float* __restrict__ tok,
                                               const float* __restrict__ pos) {
    int i = blockIdx.x;                   // bt row
    int t = i & (Tn - 1);
    int token = idx[i];
    const float4* te = (const float4*)(tok + (size_t)token * Cn);
    const float4* pe = (const float4*)(pos + (size_t)t * Cn);
    int tid = threadIdx.x;
    float4 a = te[tid], b = pe[tid];
    uint2 o;
    o.x = packh2(a.x + b.x, a.y + b.y);
    o.y = packh2(a.z + b.z, a.w + b.w);
    int r = i & 127, bm = i >> 7;
    int kc = tid >> 4;                    // k = tid*4; kc = k>>6
    int c16 = (tid >> 1) & 7;
    int hsel = tid & 1;
    size_t base = ((size_t)(bm * 16 + kc)) * 16384;
    uint32_t off = (uint32_t)r * 128 + ((unsigned)(c16 ^ (r & 7)) << 4) + hsel * 8;
    *(uint2*)((char*)g_xh + base + off) = o;
}

// ---------------------------------------------------------------------------
// 1b) W_lm -> fp16, tile-chunked + SW128-swizzled B layout. Grid-stride so it
//     trickles alongside the attention chain on the side stream.
__global__ __launch_bounds__(256) void k_w2h(const float* __restrict__ W) {
    for (int gid = blockIdx.x * 256 + threadIdx.x; gid < Vn * 128;
         gid += gridDim.x * 256) {
        int v = gid >> 7, g8 = gid & 127;             // kk = g8*8
        const float4* s = (const float4*)(W + (size_t)v * Cn + g8 * 8);
        float4 x = s[0], y = s[1];
        uint4 o;
        o.x = packh2(x.x, x.y); o.y = packh2(x.z, x.w);
        o.z = packh2(y.x, y.y); o.w = packh2(y.z, y.w);
        int bn = v >> 8, r = v & 255;
        int kc = g8 >> 3, c16 = g8 & 7;
        size_t chunkB = (((size_t)bn * 16 + kc) * (256 * 64)) * 2;
        uint32_t off = (uint32_t)r * 128 + ((unsigned)(c16 ^ (r & 7)) << 4);
        *(uint4*)((char*)g_wh + chunkB + off) = o;
    }
}

// ---------------------------------------------------------------------------
// 1c) Wq/Wk/Wv -> transposed fp16 chunked B layout (n=(h,d) rows, k=c).
__global__ __launch_bounds__(256) void k_wqkv(const float* __restrict__ Wq,
                                              const float* __restrict__ Wk,
                                              const float* __restrict__ Wv) {
    int u = blockIdx.x * 4 + (threadIdx.x >> 6);   // 0..6143
    int d = threadIdx.x & 63;
    int mat = u >> 11;
    int rem = u & 2047;
    int h = rem >> 7;
    int kc = (rem >> 3) & 15;
    int c16 = rem & 7;
    const float* W = (mat == 0) ? Wq : (mat == 1) ? Wk : Wv;
    const float* Wb = W + (size_t)h * (Cn * HDn) + d;
    float vals[8];
#pragma unroll
    for (int j = 0; j < 8; j++) {
        int c = kc * 64 + c16 * 8 + j;
        vals[j] = Wb[(size_t)c * HDn];
    }
    uint4 o;
    o.x = packh2(vals[0], vals[1]); o.y = packh2(vals[2], vals[3]);
    o.z = packh2(vals[4], vals[5]); o.w = packh2(vals[6], vals[7]);
    int bnAll = mat * 4 + (h >> 2);
    int r = (h & 3) * 64 + d;
    size_t chunkB = (((size_t)bnAll * 16 + kc) * (256 * 64)) * 2;
    uint32_t off = (uint32_t)r * 128 + ((unsigned)(c16 ^ (r & 7)) << 4);
    *(uint4*)((char*)g_wqkvh + chunkB + off) = o;
}

// ===========================================================================
// Shared fp16 bulk-pipeline GEMM pieces
// ===========================================================================
#define LKCH 16                          // K chunks of 64
#define A_CH_BYTES (128 * 128)           // 16KB
#define B_CH_BYTES (256 * 128)           // 32KB
#define LSTG_BYTES (A_CH_BYTES + B_CH_BYTES)   // 49152
#define LOG_SMEM (3 * LSTG_BYTES)        // 147456
#define OPITCH 264                       // f32 pitch for epilogue staging

struct Frags { unsigned a[4][4]; unsigned b[8][2]; };

__device__ __forceinline__ void load_frags(Frags& f, uint32_t sb, int kt,
                                           uint32_t aAddr0, uint32_t bAddr0,
                                           int gA16, int gB16, int l7) {
    const uint32_t xA = ((uint32_t)((kt * 2 + gA16) ^ l7)) << 4;
    const uint32_t xB = ((uint32_t)((kt * 2 + gB16) ^ l7)) << 4;
#pragma unroll
    for (int mt = 0; mt < 4; mt++)
        ldsm4(f.a[mt][0], f.a[mt][1], f.a[mt][2], f.a[mt][3],
              sb + aAddr0 + mt * (16 * 128) + xA);
#pragma unroll
    for (int np = 0; np < 4; np++)
        ldsm4(f.b[2 * np][0], f.b[2 * np][1], f.b[2 * np + 1][0], f.b[2 * np + 1][1],
              sb + bAddr0 + np * (16 * 128) + xB);
}

__device__ __forceinline__ void gemm_mainloop(float (&c)[4][8][4], uint32_t sbase,
                                              uint32_t mb0, const char* gA,
                                              const char* gB, int tid,
                                              uint32_t aAddr0, uint32_t bAddr0,
                                              int gA16, int gB16, int l7) {
    Frags fr[2];
    MBAR_WAIT(mb0, 0);
    load_frags(fr[0], sbase, 0, aAddr0, bAddr0, gA16, gB16, l7);

    for (int kc = 0; kc < LKCH; kc++) {
        const uint32_t sb = sbase + (kc % 3) * LSTG_BYTES;
#pragma unroll
        for (int kt = 0; kt < 4; kt++) {
            const int cur = kt & 1;
            if (kt < 3)
                load_frags(fr[cur ^ 1], sb, kt + 1, aAddr0, bAddr0, gA16, gB16, l7);
#pragma unroll
            for (int mt = 0; mt < 4; mt++)
#pragma unroll
                for (int nt = 0; nt < 8; nt++) mma16(c[mt][nt], fr[cur].a[mt], fr[cur].b[nt]);
        }
        __syncthreads();
        if (tid == 0 && kc + 3 < LKCH) {
            int s = kc % 3;
            uint32_t m = mb0 + s * 8;
            uint32_t dst = sbase + s * LSTG_BYTES;
            MBAR_EXPECT(m, LSTG_BYTES);
            bulk_g2s(dst, gA + (size_t)(kc + 3) * A_CH_BYTES, A_CH_BYTES, m);
            bulk_g2s(dst + A_CH_BYTES, gB + (size_t)(kc + 3) * B_CH_BYTES, B_CH_BYTES, m);
        }
        if (kc + 1 < LKCH) {
            MBAR_WAIT(mb0 + ((kc + 1) % 3) * 8, ((kc + 1) / 3) & 1);
            load_frags(fr[0], sbase + ((kc + 1) % 3) * LSTG_BYTES, 0,
                       aAddr0, bAddr0, gA16, gB16, l7);
        }
    }
}

// ---------------------------------------------------------------------------
// 2) QKV via fp16 bulk pipeline. grid (16, 12): bn 0-3 -> q, 4-7 -> k, 8-11 -> v.
__global__ __launch_bounds__(256, 1) void k_qkv_h() {
    extern __shared__ __align__(128) char sm[];
    __shared__ __align__(8) unsigned long long s_mb[3];
    const int tid = threadIdx.x, lane = tid & 31, wid = tid >> 5;
    const int bm = blockIdx.x, bnAll = blockIdx.y;
    const uint32_t sbase = smem_u32(sm);
    const uint32_t mb0 = smem_u32(&s_mb[0]);

    if (tid == 0) {
        MBAR_INIT(mb0, 1);
        MBAR_INIT(mb0 + 8, 1);
        MBAR_INIT(mb0 + 16, 1);
    }
    __syncthreads();

    const char* gA = (const char*)g_xh + ((size_t)bm * LKCH) * A_CH_BYTES;
    const char* gB = (const char*)g_wqkvh + ((size_t)bnAll * LKCH) * B_CH_BYTES;

    if (tid == 0) {
#pragma unroll
        for (int s = 0; s < 3; s++) {
            uint32_t m = mb0 + s * 8;
            uint32_t dst = sbase + s * LSTG_BYTES;
            MBAR_EXPECT(m, LSTG_BYTES);
            bulk_g2s(dst, gA + (size_t)s * A_CH_BYTES, A_CH_BYTES, m);
            bulk_g2s(dst + A_CH_BYTES, gB + (size_t)s * B_CH_BYTES, B_CH_BYTES, m);
        }
    }

    float c[4][8][4];
#pragma unroll
    for (int mt = 0; mt < 4; mt++)
#pragma unroll
        for (int nt = 0; nt < 8; nt++)
#pragma unroll
            for (int e = 0; e < 4; e++) c[mt][nt][e] = 0.f;

    const int wm0 = (wid >> 2) * 64, wn0 = (wid & 3) * 64;
    const int l7 = lane & 7;
    const uint32_t aAddr0 = (uint32_t)(wm0 + (lane & 15)) * 128;
    const uint32_t bAddr0 = A_CH_BYTES +
                            (uint32_t)(wn0 + ((lane >> 4) << 3) + l7) * 128;
    const int gA16 = lane >> 4, gB16 = (lane >> 3) & 1;

    gemm_mainloop(c, sbase, mb0, gA, gB, tid, aAddr0, bAddr0, gA16, gB16, l7);

    // stage (scaled) accum to SMEM f32
    const int mat = bnAll >> 2;
    const float sc = (mat == 0) ? 0.03125f : 1.0f;
    __syncthreads();
    float* so = (float*)sm;
    const int g = lane >> 2, tig = lane & 3;
#pragma unroll
    for (int mt = 0; mt < 4; mt++)
#pragma unroll
        for (int e2 = 0; e2 < 2; e2++) {
            int rl = wm0 + mt * 16 + g + e2 * 8;
#pragma unroll
            for (int nt = 0; nt < 8; nt++) {
                int cl = wn0 + nt * 8 + 2 * tig;
                float2 w;
                w.x = c[mt][nt][e2 * 2 + 0] * sc;
                w.y = c[mt][nt][e2 * 2 + 1] * sc;
                *(float2*)(so + rl * OPITCH + cl) = w;
            }
        }
    __syncthreads();

    const int b = bm >> 3;            // batch of this 128-row tile
    if (mat < 2) {
        // Q/K: [bh][sb][r:128][64] chunks; warp handles rows wid*16..+15
        __half* dst = (mat == 0) ? g_qh : g_kh;
        const int seg = lane >> 3, g8 = lane & 7;
        const int h = (bnAll & 3) * 4 + seg;
        const int sb = bm & 7;
#pragma unroll 1
        for (int rr = 0; rr < 16; rr++) {
            int rl = wid * 16 + rr;
            const float* srow = so + rl * OPITCH + seg * 64 + g8 * 8;
            uint4 o;
            o.x = packh2(srow[0], srow[1]); o.y = packh2(srow[2], srow[3]);
            o.z = packh2(srow[4], srow[5]); o.w = packh2(srow[6], srow[7]);
            size_t chunk = ((size_t)((b * 16 + h) * 8 + sb)) * 16384;
            uint32_t off = (uint32_t)rl * 128 + ((unsigned)(g8 ^ (rl & 7)) << 4);
            *(uint4*)((char*)dst + chunk + off) = o;
        }
    } else {
        // V^T: [bh][skc:16][d:64][64 s] chunks of 8KB
#pragma unroll 1
        for (int it = 0; it < 16; it++) {
            int u = tid * 16 + it;
            int seg = u >> 10;
            int d = (u >> 4) & 63;
            int sg = u & 15;              // s granule of 8 within 128 rows
            const float* scol = so + (sg * 8) * OPITCH + seg * 64 + d;
            uint4 o;
            o.x = packh2(scol[0], scol[OPITCH]);
            o.y = packh2(scol[2 * OPITCH], scol[3 * OPITCH]);
            o.z = packh2(scol[4 * OPITCH], scol[5 * OPITCH]);
            o.w = packh2(scol[6 * OPITCH], scol[7 * OPITCH]);
            int h = (bnAll & 3) * 4 + seg;
            int skc = (bm & 7) * 2 + (sg >> 3);
            size_t chunk = ((size_t)((b * 16 + h) * 16 + skc)) * 8192;
            uint32_t off = (uint32_t)d * 128 + ((unsigned)((sg & 7) ^ (d & 7)) << 4);
            *(uint4*)((char*)g_vt + chunk + off) = o;
        }
    }
}

// ---------------------------------------------------------------------------
// 3) Fused flash attention with PAIRED tiles: CTA (pair, bh) handles
//    bm_hi = 7-pair then bm_lo = pair -> exactly 9 kv-blocks per CTA.
//    grid = 128 CTAs = one balanced wave.
#define FQ_BYTES 16384
#define FKV_BYTES 32768                  // K 16KB + V^T 16KB
#define FLASH_SMEM (FQ_BYTES + 2 * FKV_BYTES)   // 81920

__global__ __launch_bounds__(256, 1) void k_flash() {
    extern __shared__ __align__(128) char sm[];
    __shared__ __align__(8) unsigned long long s_mb[3];   // Q, stage0, stage1
    const int tid = threadIdx.x, lane = tid & 31, wid = tid >> 5;
    const int pair = blockIdx.x >> 5;         // 0..3
    const int bh = blockIdx.x & 31;
    const int bm_hi = 7 - pair, bm_lo = pair; // (bm_hi+1)+(bm_lo+1) = 9
    const uint32_t sbase = smem_u32(sm);
    const uint32_t mbQ = smem_u32(&s_mb[0]);

    const char* gQb = (const char*)g_qh + ((size_t)bh * 8) * 16384;
    const char* gK = (const char*)g_kh + ((size_t)bh * 8) * 16384;
    const char* gV = (const char*)g_vt + ((size_t)bh * 16) * 8192;

    if (tid == 0) {
        MBAR_INIT(mbQ, 1);
        MBAR_INIT(mbQ + 8, 1);
        MBAR_INIT(mbQ + 16, 1);
    }
    __syncthreads();
    if (tid == 0) {
        MBAR_EXPECT(mbQ, FQ_BYTES);
        bulk_g2s(sbase, gQb + (size_t)bm_hi * 16384, FQ_BYTES, mbQ);
        MBAR_EXPECT(mbQ + 8, FKV_BYTES);
        bulk_g2s(sbase + FQ_BYTES, gK, 16384, mbQ + 8);
        bulk_g2s(sbase + FQ_BYTES + 16384, gV, 16384, mbQ + 8);
        MBAR_EXPECT(mbQ + 16, FKV_BYTES);
        bulk_g2s(sbase + FQ_BYTES + FKV_BYTES, gK + 16384, 16384, mbQ + 16);
        bulk_g2s(sbase + FQ_BYTES + FKV_BYTES + 16384, gV + 16384, 16384, mbQ + 16);
    }

    const int wm = wid * 16;
    const int l7 = lane & 7;
    const int g = lane >> 2, tig = lane & 3;
    const uint32_t aAddr0 = (uint32_t)(wm + (lane & 15)) * 128;
    const uint32_t rowBB = (uint32_t)(((lane >> 4) << 3) + l7) * 128;
    const int gA16 = lane >> 4, gB16 = (lane >> 3) & 1;

    float m0 = -1e30f, m1 = -1e30f, l0 = 0.f, l1 = 0.f;
    float o[8][4];
#pragma unroll
    for (int nt = 0; nt < 8; nt++)
#pragma unroll
        for (int e = 0; e < 4; e++) o[nt][e] = 0.f;

    unsigned aq[4][4];
    MBAR_WAIT(mbQ, 0);
#pragma unroll
    for (int kt = 0; kt < 4; kt++) {
        uint32_t xA = ((uint32_t)((kt * 2 + gA16) ^ l7)) << 4;
        ldsm4(aq[kt][0], aq[kt][1], aq[kt][2], aq[kt][3], sbase + aAddr0 + xA);
    }
    __syncthreads();                 // all warps have read Q_hi from smem
    if (tid == 0) {                  // prefetch Q_lo into the (now free) Q buffer
        MBAR_EXPECT(mbQ, FQ_BYTES);
        bulk_g2s(sbase, gQb + (size_t)bm_lo * 16384, FQ_BYTES, mbQ);
    }

    const int b = bh >> 4, h = bh & 15;

    auto write_out = [&](int bm_out) {
        const float inv0 = 1.0f / l0, inv1 = 1.0f / l1;
        const size_t chunkB = ((size_t)((b * 8 + bm_out) * 16 + h)) * 16384;
#pragma unroll
        for (int nt = 0; nt < 8; nt++)
#pragma unroll
            for (int e = 0; e < 4; e++) {
                int rl = wm + g + ((e >= 2) ? 8 : 0);
                int d = nt * 8 + 2 * tig + (e & 1);
                float val = o[nt][e] * ((e >= 2) ? inv1 : inv0);
                uint32_t off = (uint32_t)rl * 128 +
                               ((unsigned)(((d >> 3) ^ (rl & 7))) << 4) + (d & 7) * 2;
                *(__half*)((char*)g_ah + chunkB + off) = __float2half_rn(val);
            }
    };

    for (int i = 0; i < 9; i++) {
        const int in_hi = (i <= bm_hi);
        const int cur_bm = in_hi ? bm_hi : bm_lo;
        const int j = in_hi ? i : (i - bm_hi - 1);
        const uint32_t stg = sbase + FQ_BYTES + (i & 1) * FKV_BYTES;
        MBAR_WAIT(mbQ + 8 + (i & 1) * 8, (i >> 1) & 1);

        float s[16][4];
#pragma unroll
        for (int nt = 0; nt < 16; nt++)
#pragma unroll
            for (int e = 0; e < 4; e++) s[nt][e] = 0.f;

#pragma unroll
        for (int kt = 0; kt < 4; kt++) {
            uint32_t xB = ((uint32_t)((kt * 2 + gB16) ^ l7)) << 4;
            unsigned bk[16][2];
#pragma unroll
            for (int np = 0; np < 8; np++)
                ldsm4(bk[2 * np][0], bk[2 * np][1], bk[2 * np + 1][0], bk[2 * np + 1][1],
                      stg + rowBB + np * (16 * 128) + xB);
#pragma unroll
            for (int nt = 0; nt < 16; nt++) mma16(s[nt], aq[kt], bk[nt]);
        }

        if (j == cur_bm) {   // causal mask on diagonal block
#pragma unroll
            for (int nt = 0; nt < 16; nt++) {
                int col = nt * 8 + 2 * tig;
                int r0 = wm + g, r1 = wm + g + 8;
                if (col > r0)     s[nt][0] = -1e30f;
                if (col + 1 > r0) s[nt][1] = -1e30f;
                if (col > r1)     s[nt][2] = -1e30f;
                if (col + 1 > r1) s[nt][3] = -1e30f;
            }
        }

        // online softmax
        float v0 = -1e30f, v1 = -1e30f;
#pragma unroll
        for (int nt = 0; nt < 16; nt++) {
            v0 = fmaxf(v0, fmaxf(s[nt][0], s[nt][1]));
            v1 = fmaxf(v1, fmaxf(s[nt][2], s[nt][3]));
        }
#pragma unroll
        for (int off = 1; off <= 2; off <<= 1) {
            v0 = fmaxf(v0, __shfl_xor_sync(0xffffffffu, v0, off));
            v1 = fmaxf(v1, __shfl_xor_sync(0xffffffffu, v1, off));
        }
        float mn0 = fmaxf(m0, v0), mn1 = fmaxf(m1, v1);
        float sc0 = __expf(m0 - mn0), sc1 = __expf(m1 - mn1);
        float sum0 = 0.f, sum1 = 0.f;
#pragma unroll
        for (int nt = 0; nt < 16; nt++) {
            s[nt][0] = __expf(s[nt][0] - mn0);
            s[nt][1] = __expf(s[nt][1] - mn0);
            s[nt][2] = __expf(s[nt][2] - mn1);
            s[nt][3] = __expf(s[nt][3] - mn1);
            sum0 += s[nt][0] + s[nt][1];
            sum1 += s[nt][2] + s[nt][3];
        }
#pragma unroll
        for (int off = 1; off <= 2; off <<= 1) {
            sum0 += __shfl_xor_sync(0xffffffffu, sum0, off);
            sum1 += __shfl_xor_sync(0xffffffffu, sum1, off);
        }
        l0 = l0 * sc0 + sum0; l1 = l1 * sc1 + sum1;
        m0 = mn0; m1 = mn1;
#pragma unroll
        for (int nt = 0; nt < 8; nt++) {
            o[nt][0] *= sc0; o[nt][1] *= sc0;
            o[nt][2] *= sc1; o[nt][3] *= sc1;
        }

        // pack P as A-fragments
        unsigned pa[8][4];
#pragma unroll
        for (int kt = 0; kt < 8; kt++) {
            pa[kt][0] = packh2(s[2 * kt][0], s[2 * kt][1]);
            pa[kt][1] = packh2(s[2 * kt][2], s[2 * kt][3]);
            pa[kt][2] = packh2(s[2 * kt + 1][0], s[2 * kt + 1][1]);
            pa[kt][3] = packh2(s[2 * kt + 1][2], s[2 * kt + 1][3]);
        }

        // PV: V^T tiles (n=d 64, k=s 128 in two 64-k chunks)
#pragma unroll
        for (int kt = 0; kt < 8; kt++) {
            const uint32_t vb = stg + 16384 + (kt >> 2) * 8192;
            const int kt2 = kt & 3;
            uint32_t xV = ((uint32_t)((kt2 * 2 + gB16) ^ l7)) << 4;
            unsigned bv[8][2];
#pragma unroll
            for (int np = 0; np < 4; np++)
                ldsm4(bv[2 * np][0], bv[2 * np][1], bv[2 * np + 1][0], bv[2 * np + 1][1],
                      vb + rowBB + np * (16 * 128) + xV);
#pragma unroll
            for (int nt = 0; nt < 8; nt++) mma16(o[nt], pa[kt], bv[nt]);
        }

        __syncthreads();
        if (tid == 0 && i + 2 < 9) {
            int jn = (i + 2 <= bm_hi) ? (i + 2) : (i + 2 - bm_hi - 1);
            int st = i & 1;
            uint32_t m = mbQ + 8 + st * 8;
            uint32_t dst = sbase + FQ_BYTES + st * FKV_BYTES;
            MBAR_EXPECT(m, FKV_BYTES);
            bulk_g2s(dst, gK + (size_t)jn * 16384, 16384, m);
            bulk_g2s(dst + 16384, gV + (size_t)jn * 16384, 16384, m);
        }

        if (i == bm_hi) {
            write_out(bm_hi);
            m0 = -1e30f; m1 = -1e30f; l0 = 0.f; l1 = 0.f;
#pragma unroll
            for (int nt = 0; nt < 8; nt++)
#pragma unroll
                for (int e = 0; e < 4; e++) o[nt][e] = 0.f;
            MBAR_WAIT(mbQ, 1);
#pragma unroll
            for (int kt = 0; kt < 4; kt++) {
                uint32_t xA = ((uint32_t)((kt * 2 + gA16) ^ l7)) << 4;
                ldsm4(aq[kt][0], aq[kt][1], aq[kt][2], aq[kt][3], sbase + aAddr0 + xA);
            }
        }
    }

    write_out(bm_lo);
}

// ---------------------------------------------------------------------------
// 4) LM head: fp16 bulk pipeline (the R12 601.8us winner, restored verbatim)
__global__ __launch_bounds__(256, 1) void k_logits_b(const float* __restrict__ blm,
                                                     float* __restrict__ out) {
    extern __shared__ __align__(128) char sm[];
    __shared__ float s_bias[256];
    __shared__ __align__(8) unsigned long long s_mb[3];
    const int tid = threadIdx.x, lane = tid & 31, wid = tid >> 5;
    const int bm = blockIdx.x, bn = blockIdx.y;
    const uint32_t sbase = smem_u32(sm);
    const uint32_t mb0 = smem_u32(&s_mb[0]);

    {
        int gc = bn * 256 + tid;
        s_bias[tid] = (gc < Vn) ? blm[gc] : 0.f;
    }
    if (tid == 0) {
        MBAR_INIT(mb0, 1);
        MBAR_INIT(mb0 + 8, 1);
        MBAR_INIT(mb0 + 16, 1);
    }
    __syncthreads();

    const char* gA = (const char*)g_ah + ((size_t)bm * LKCH) * A_CH_BYTES;
    const char* gB = (const char*)g_wh + ((size_t)bn * LKCH) * B_CH_BYTES;

    if (tid == 0) {
#pragma unroll
        for (int s = 0; s < 3; s++) {
            uint32_t m = mb0 + s * 8;
            uint32_t dst = sbase + s * LSTG_BYTES;
            MBAR_EXPECT(m, LSTG_BYTES);
            bulk_g2s(dst, gA + (size_t)s * A_CH_BYTES, A_CH_BYTES, m);
            bulk_g2s(dst + A_CH_BYTES, gB + (size_t)s * B_CH_BYTES, B_CH_BYTES, m);
        }
    }

    float c[4][8][4];
#pragma unroll
    for (int mt = 0; mt < 4; mt++)
#pragma unroll
        for (int nt = 0; nt < 8; nt++)
#pragma unroll
            for (int e = 0; e < 4; e++) c[mt][nt][e] = 0.f;

    const int wm0 = (wid >> 2) * 64, wn0 = (wid & 3) * 64;
    const int l7 = lane & 7;
    const uint32_t aAddr0 = (uint32_t)(wm0 + (lane & 15)) * 128;
    const uint32_t bAddr0 = A_CH_BYTES +
                            (uint32_t)(wn0 + ((lane >> 4) << 3) + l7) * 128;
    const int gA16 = lane >> 4, gB16 = (lane >> 3) & 1;

    gemm_mainloop(c, sbase, mb0, gA, gB, tid, aAddr0, bAddr0, gA16, gB16, l7);

    __syncthreads();
    float* so = (float*)sm;
    const int g = lane >> 2, tig = lane & 3;
#pragma unroll
    for (int mt = 0; mt < 4; mt++)
#pragma unroll
        for (int e2 = 0; e2 < 2; e2++) {
            int rl = wm0 + mt * 16 + g + e2 * 8;
#pragma unroll
            for (int nt = 0; nt < 8; nt++) {
                int cl = wn0 + nt * 8 + 2 * tig;
                float2 w;
                w.x = c[mt][nt][e2 * 2 + 0] + s_bias[cl];
                w.y = c[mt][nt][e2 * 2 + 1] + s_bias[cl + 1];
                *(float2*)(so + rl * OPITCH + cl) = w;
            }
        }
    __syncthreads();
#pragma unroll 1
    for (int rr = 0; rr < 16; rr++) {
        int rl = wid * 16 + rr;
        int row = bm * 128 + rl;
        float* orow = out + (size_t)row * Vn;
        const float* srow = so + rl * OPITCH;
#pragma unroll
        for (int j = 0; j < 8; j++) {
            int cl = lane + j * 32;
            int col = bn * 256 + cl;
            if (col < Vn) orow[col] = srow[cl];
        }
    }
}

// ---------------------------------------------------------------------------
extern "C" void kernel_launch(void* const* d_in, const int* in_sizes, int n_in,
                              void* d_out, int out_size) {
    (void)in_sizes; (void)n_in; (void)out_size;
    const int*   idx = (const int*)d_in[0];
    const float* tok = (const float*)d_in[1];
    const float* pos = (const float*)d_in[2];
    const float* Wq  = (const float*)d_in[3];
    const float* Wk  = (const float*)d_in[4];
    const float* Wv  = (const float*)d_in[5];
    const float* Wlm = (const float*)d_in[6];
    const float* blm = (const float*)d_in[7];
    float* out = (float*)d_out;

    cudaFuncSetAttribute(k_logits_b, cudaFuncAttributeMaxDynamicSharedMemorySize,
                         LOG_SMEM);
    cudaFuncSetAttribute(k_qkv_h, cudaFuncAttributeMaxDynamicSharedMemorySize,
                         LOG_SMEM);
    cudaFuncSetAttribute(k_flash, cudaFuncAttributeMaxDynamicSharedMemorySize,
                         FLASH_SMEM);

    // One-time stream/event setup (runs on the first, non-captured call).
    static cudaStream_t s_side = nullptr;
    static cudaEvent_t ev_fork = nullptr, ev_join = nullptr;
    if (!s_side) {
        cudaStreamCreateWithFlags(&s_side, cudaStreamNonBlocking);
        cudaEventCreateWithFlags(&ev_fork, cudaEventDisableTiming);
        cudaEventCreateWithFlags(&ev_join, cudaEventDisableTiming);
    }

    // Fork: W_lm fp16 conversion trickles (grid-stride, 592 CTAs) alongside the
    // attention chain; only k_logits_b consumes g_wh, so join right before it.
    cudaEventRecord(ev_fork, 0);
    cudaStreamWaitEvent(s_side, ev_fork, 0);
    k_w2h<<<592, 256, 0, s_side>>>(Wlm);
    cudaEventRecord(ev_join, s_side);

    k_wqkv<<<1536, 256>>>(Wq, Wk, Wv);
    k_embed<<<BTn, 256>>>(idx, tok, pos);
    k_qkv_h<<<dim3(16, 12), 256, LOG_SMEM>>>();
    k_flash<<<128, 256, FLASH_SMEM>>>();

    cudaStreamWaitEvent(0, ev_join, 0);
    k_logits_b<<<dim3(16, NBN), 256, LOG_SMEM>>>(blm, out);
}